// round 1
// baseline (speedup 1.0000x reference)
#include <cuda_runtime.h>

#define EMB   2048
#define NSTEP 2048
#define NB    2
#define G4    (4*EMB)

#define CTAS  128
#define EPC   16          // e-values per CTA
#define NROWS 64          // 4 gates * EPC
#define NTHR  512         // 16 warps
#define RPW   4           // rows per warp

// K partition per row: [0,512) registers, [512,1280) smem, [1280,2048) L2
#define KRF_J   16        // j iters with k = lane + 32*j, j in [0,16)
#define KSM_J0  16
#define KSM_J1  40        // smem covers j in [16,40)  -> k in [512,1280)
#define KL2_J1  64        // L2 covers j in [40,64)
#define KSM_LEN 768

// dynamic smem layout (floats)
#define SH_H_OFF 0
#define SH_W_OFF (2*EMB)
#define SH_G_OFF (2*EMB + NROWS*KSM_LEN)
#define SMEM_FLOATS (2*EMB + NROWS*KSM_LEN + NROWS*2)
#define SMEM_BYTES  (SMEM_FLOATS*4)

__device__ float    g_Wcomb[(size_t)G4*EMB];     // 67 MB
__device__ float    g_bcomb[G4];
__device__ float    g_hseq[(size_t)NSTEP*NB*EMB]; // 33.5 MB, [t][b][e]
__device__ unsigned g_bar;

// ---------------------------------------------------------------------------
// prep: W_comb = W_ih + W_hh, b_comb = b_ih + b_hh, reset barrier
// ---------------------------------------------------------------------------
__global__ void prep_kernel(const float* __restrict__ Wih, const float* __restrict__ Whh,
                            const float* __restrict__ bih, const float* __restrict__ bhh) {
    size_t n = (size_t)G4 * EMB;
    size_t stride = (size_t)gridDim.x * blockDim.x;
    for (size_t i = (size_t)blockIdx.x * blockDim.x + threadIdx.x; i < n; i += stride)
        g_Wcomb[i] = Wih[i] + Whh[i];
    int i = blockIdx.x * blockDim.x + threadIdx.x;
    if (i < G4) g_bcomb[i] = bih[i] + bhh[i];
    if (i == 0) g_bar = 0u;
}

__device__ __forceinline__ float sigmoidf_(float v) {
    return 1.0f / (1.0f + expf(-v));
}

// ---------------------------------------------------------------------------
// persistent LSTM kernel: 128 CTAs x 512 threads, one CTA per SM guaranteed
// (smem 208KB => occupancy 1, grid 128 <= 148 SMs => all resident)
// ---------------------------------------------------------------------------
__global__ void __launch_bounds__(NTHR, 1)
lstm_kernel(const float* __restrict__ x, const float* __restrict__ Wih) {
    extern __shared__ float sh[];
    float* sh_h = sh + SH_H_OFF;   // [2][EMB]
    float* sh_w = sh + SH_W_OFF;   // [NROWS][KSM_LEN]
    float* sh_g = sh + SH_G_OFF;   // [NROWS][2]

    const int tid  = threadIdx.x;
    const int lane = tid & 31;
    const int wid  = tid >> 5;
    const int e0   = blockIdx.x * EPC;

    // row assignment: r_local = wid*4 + r; gate = r_local>>4, e_l = r_local&15
    int rl[RPW], Rg[RPW];
    float bias[RPW];
#pragma unroll
    for (int r = 0; r < RPW; r++) {
        rl[r] = wid * RPW + r;
        int gate = rl[r] >> 4, e_l = rl[r] & 15;
        Rg[r] = gate * EMB + e0 + e_l;        // global gate-row in [0, 8192)
        bias[r] = g_bcomb[Rg[r]];
    }

    // register-resident weights: k = lane + 32*j, j in [0,16)
    float wreg[RPW][KRF_J];
#pragma unroll
    for (int r = 0; r < RPW; r++)
#pragma unroll
        for (int j = 0; j < KRF_J; j++)
            wreg[r][j] = g_Wcomb[(size_t)Rg[r] * EMB + (lane + 32 * j)];

    // smem-resident weights: k in [512,1280) for all 64 rows (192 KB)
    {
        const int n4 = NROWS * (KSM_LEN / 4);   // 12288 float4
        for (int i = tid; i < n4; i += NTHR) {
            int rr = i / (KSM_LEN / 4);
            int c4 = i % (KSM_LEN / 4);
            int grow = ((rr >> 4) * EMB) + e0 + (rr & 15);
            float4 v = *(const float4*)&g_Wcomb[(size_t)grow * EMB + 512 + c4 * 4];
            *(float4*)&sh_w[rr * KSM_LEN + c4 * 4] = v;
        }
    }

    // cell state: thread tid<32 owns (e_l = tid>>1, b = tid&1)
    float c_reg = 0.0f;
    const int my_el = tid >> 1, my_b = tid & 1;

    for (int t = 0; t < NSTEP; t++) {
        // load h_{t-1} (or x for step 0) into smem
        const float* src = (t == 0) ? x : &g_hseq[(size_t)(t - 1) * NB * EMB];
        for (int i = tid; i < (NB * EMB) / 4; i += NTHR) {
            float4 v = __ldcg(((const float4*)src) + i);   // bypass L1 (cross-CTA data)
            ((float4*)sh_h)[i] = v;
        }
        __syncthreads();

        float acc[RPW][2];
#pragma unroll
        for (int r = 0; r < RPW; r++) { acc[r][0] = 0.0f; acc[r][1] = 0.0f; }

        if (t == 0) {
            // gates0 = x @ W_ih^T + b_comb   (h0 = 0 kills the W_hh term)
#pragma unroll 4
            for (int j = 0; j < 64; j++) {
                int k = lane + 32 * j;
                float h0 = sh_h[k], h1 = sh_h[EMB + k];
#pragma unroll
                for (int r = 0; r < RPW; r++) {
                    float w = __ldg(&Wih[(size_t)Rg[r] * EMB + k]);
                    acc[r][0] += w * h0; acc[r][1] += w * h1;
                }
            }
        } else {
            // phase 1: register weights
#pragma unroll
            for (int j = 0; j < KRF_J; j++) {
                int k = lane + 32 * j;
                float h0 = sh_h[k], h1 = sh_h[EMB + k];
#pragma unroll
                for (int r = 0; r < RPW; r++) {
                    float w = wreg[r][j];
                    acc[r][0] += w * h0; acc[r][1] += w * h1;
                }
            }
            // phase 2: smem weights, k in [512,1280)
#pragma unroll 4
            for (int j = KSM_J0; j < KSM_J1; j++) {
                int k = lane + 32 * j;
                float h0 = sh_h[k], h1 = sh_h[EMB + k];
#pragma unroll
                for (int r = 0; r < RPW; r++) {
                    float w = sh_w[rl[r] * KSM_LEN + (k - 512)];
                    acc[r][0] += w * h0; acc[r][1] += w * h1;
                }
            }
            // phase 3: L2 weights, k in [1280,2048)
#pragma unroll 6
            for (int j = KSM_J1; j < KL2_J1; j++) {
                int k = lane + 32 * j;
                float h0 = sh_h[k], h1 = sh_h[EMB + k];
#pragma unroll
                for (int r = 0; r < RPW; r++) {
                    float w = __ldg(&g_Wcomb[(size_t)Rg[r] * EMB + k]);
                    acc[r][0] += w * h0; acc[r][1] += w * h1;
                }
            }
        }

        // warp reduce + write gate values
#pragma unroll
        for (int r = 0; r < RPW; r++)
#pragma unroll
            for (int b = 0; b < 2; b++) {
                float v = acc[r][b];
                v += __shfl_xor_sync(0xffffffffu, v, 16);
                v += __shfl_xor_sync(0xffffffffu, v, 8);
                v += __shfl_xor_sync(0xffffffffu, v, 4);
                v += __shfl_xor_sync(0xffffffffu, v, 2);
                v += __shfl_xor_sync(0xffffffffu, v, 1);
                if (lane == 0) sh_g[rl[r] * 2 + b] = v + bias[r];
            }
        __syncthreads();

        // nonlinearity + state update (PyTorch gate order i,f,g,o)
        if (tid < 32) {
            float gi = sh_g[(0  + my_el) * 2 + my_b];
            float gf = sh_g[(16 + my_el) * 2 + my_b];
            float gg = sh_g[(32 + my_el) * 2 + my_b];
            float go = sh_g[(48 + my_el) * 2 + my_b];
            float cn = sigmoidf_(gf) * c_reg + sigmoidf_(gi) * tanhf(gg);
            c_reg = cn;
            float h = sigmoidf_(go) * tanhf(cn);
            g_hseq[((size_t)t * NB + my_b) * EMB + e0 + my_el] = h;
        }
        __threadfence();
        __syncthreads();

        // software grid barrier (all 128 CTAs resident by construction)
        if (tid == 0) {
            atomicAdd(&g_bar, 1u);
            unsigned target = (unsigned)(t + 1) * gridDim.x;
            while (*((volatile unsigned*)&g_bar) < target) { }
            __threadfence();
        }
        __syncthreads();
    }
}

// ---------------------------------------------------------------------------
// output projection: out[b][t][n] = hseq[t][b][:] . W_out[n][:] + b_out[n]
// M = 4096 (m = t*2+b), N = 2048, K = 2048
// ---------------------------------------------------------------------------
#define GBM 64
#define GBN 64
#define GBK 16
#define GPAD 4

__global__ void __launch_bounds__(256)
out_gemm_kernel(const float* __restrict__ Wout, const float* __restrict__ bout,
                float* __restrict__ out) {
    __shared__ float As[GBK][GBM + GPAD];
    __shared__ float Bs[GBK][GBN + GPAD];

    const int tid = threadIdx.x;
    const int tx = tid & 15;   // n dir
    const int ty = tid >> 4;   // m dir
    const int m0 = blockIdx.y * GBM;
    const int n0 = blockIdx.x * GBN;

    float acc[4][4];
#pragma unroll
    for (int i = 0; i < 4; i++)
#pragma unroll
        for (int j = 0; j < 4; j++) acc[i][j] = 0.0f;

    const int lm = tid >> 2;          // 0..63
    const int lk = (tid & 3) * 4;     // 0,4,8,12

    for (int k0 = 0; k0 < EMB; k0 += GBK) {
        float4 va = *(const float4*)&g_hseq[(size_t)(m0 + lm) * EMB + k0 + lk];
        float4 vb = *(const float4*)&Wout[(size_t)(n0 + lm) * EMB + k0 + lk];
        As[lk + 0][lm] = va.x; As[lk + 1][lm] = va.y;
        As[lk + 2][lm] = va.z; As[lk + 3][lm] = va.w;
        Bs[lk + 0][lm] = vb.x; Bs[lk + 1][lm] = vb.y;
        Bs[lk + 2][lm] = vb.z; Bs[lk + 3][lm] = vb.w;
        __syncthreads();

#pragma unroll
        for (int k = 0; k < GBK; k++) {
            float a0 = As[k][ty * 4 + 0];
            float a1 = As[k][ty * 4 + 1];
            float a2 = As[k][ty * 4 + 2];
            float a3 = As[k][ty * 4 + 3];
            float4 b4 = *(const float4*)&Bs[k][tx * 4];
            acc[0][0] += a0 * b4.x; acc[0][1] += a0 * b4.y; acc[0][2] += a0 * b4.z; acc[0][3] += a0 * b4.w;
            acc[1][0] += a1 * b4.x; acc[1][1] += a1 * b4.y; acc[1][2] += a1 * b4.z; acc[1][3] += a1 * b4.w;
            acc[2][0] += a2 * b4.x; acc[2][1] += a2 * b4.y; acc[2][2] += a2 * b4.z; acc[2][3] += a2 * b4.w;
            acc[3][0] += a3 * b4.x; acc[3][1] += a3 * b4.y; acc[3][2] += a3 * b4.z; acc[3][3] += a3 * b4.w;
        }
        __syncthreads();
    }

#pragma unroll
    for (int i = 0; i < 4; i++) {
        int m = m0 + ty * 4 + i;
        int tt = m >> 1, bb = m & 1;
#pragma unroll
        for (int j = 0; j < 4; j++) {
            int n = n0 + tx * 4 + j;
            out[((size_t)bb * NSTEP + tt) * EMB + n] = acc[i][j] + bout[n];
        }
    }
}

// ---------------------------------------------------------------------------
extern "C" void kernel_launch(void* const* d_in, const int* in_sizes, int n_in,
                              void* d_out, int out_size) {
    const float* x    = (const float*)d_in[0];   // [2, 2048]
    const float* Wih  = (const float*)d_in[1];   // [8192, 2048]
    const float* Whh  = (const float*)d_in[2];   // [8192, 2048]
    const float* bih  = (const float*)d_in[3];   // [8192]
    const float* bhh  = (const float*)d_in[4];   // [8192]
    const float* Wout = (const float*)d_in[5];   // [2048, 2048]
    const float* bout = (const float*)d_in[6];   // [2048]
    float* out = (float*)d_out;                  // [2, 2048, 2048]

    cudaFuncSetAttribute(lstm_kernel, cudaFuncAttributeMaxDynamicSharedMemorySize, SMEM_BYTES);

    prep_kernel<<<4096, 256>>>(Wih, Whh, bih, bhh);
    lstm_kernel<<<CTAS, NTHR, SMEM_BYTES>>>(x, Wih);
    dim3 ggrid(EMB / GBN, (NSTEP * NB) / GBM);
    out_gemm_kernel<<<ggrid, 256>>>(Wout, bout, out);
}